// round 12
// baseline (speedup 1.0000x reference)
#include <cuda_runtime.h>
#include <cuda_bf16.h>
#include <cstdint>
#include <cstddef>

// ---------------- problem constants ----------------
#define B_SZ   256
#define T_SZ   1024
#define I_SZ   128
#define H_SZ   256
#define CLC    8                 // CTAs per cluster (hidden split)
#define GRID_CTAS 128
#define THREADS2 512             // recurrent kernel: 16 warps = 2 groups
#define NBG    8                 // batch rows per group

// ---------------- recurrent kernel SMEM ----------------
#define SA2 520                              // 1040B = 65*16B odd -> conflict-free ldmatrix
#define A_BYTES2  (128 * SA2 * 2)            // 133120
#define MBAR_OFF  A_BYTES2                   // 133120
#define SMEM2     (MBAR_OFF + 64)            // 133184

// ---------------- precompute kernel SMEM ----------------
#define SA3 264                              // 528B = 33*16B odd
#define PC_A_BYTES (128 * SA3 * 2)           // 67584 (x tile, M=128)
#define PC_B_BYTES (256 * SA3 * 2)           // 135168 (W tile, N=256)
#define SMEM3 (PC_A_BYTES + PC_B_BYTES)      // 202752

// x-projection scratch: xp[t*B + b][g*256 + h], fp32, 1 GiB
__device__ float g_xproj[268435456];
// packed (hi | lo<<16) bf16 short-state exchange, ping-pong, in L2
__device__ uint32_t g_short_pack[2][B_SZ * H_SZ];
// pre-split, transposed x-weights: [gate][h=256][k=128] packed (hi | lo<<16)
__device__ uint32_t g_wxt[4][256 * 128];

// ---------------- helpers ----------------
__device__ __forceinline__ uint32_t smem_u32(const void* p) {
    uint32_t a;
    asm("{ .reg .u64 t; cvta.to.shared.u64 t, %1; cvt.u32.u64 %0, t; }" : "=r"(a) : "l"(p));
    return a;
}
__device__ __forceinline__ void cluster_sync() {
    asm volatile("barrier.cluster.arrive.aligned;" ::: "memory");
    asm volatile("barrier.cluster.wait.aligned;"   ::: "memory");
}
__device__ __forceinline__ void ldsm4(uint32_t* r, uint32_t addr) {
    asm volatile("ldmatrix.sync.aligned.m8n8.x4.shared.b16 {%0,%1,%2,%3}, [%4];"
                 : "=r"(r[0]), "=r"(r[1]), "=r"(r[2]), "=r"(r[3]) : "r"(addr));
}
__device__ __forceinline__ void mma16816(float* d, const uint32_t* a, const uint32_t* b) {
    asm volatile("mma.sync.aligned.m16n8k16.row.col.f32.bf16.bf16.f32 "
                 "{%0,%1,%2,%3}, {%4,%5,%6,%7}, {%8,%9}, {%0,%1,%2,%3};"
                 : "+f"(d[0]), "+f"(d[1]), "+f"(d[2]), "+f"(d[3])
                 : "r"(a[0]), "r"(a[1]), "r"(a[2]), "r"(a[3]), "r"(b[0]), "r"(b[1]));
}
__device__ __forceinline__ void mbar_init(uint32_t mbar, uint32_t cnt) {
    asm volatile("mbarrier.init.shared.b64 [%0], %1;" :: "r"(mbar), "r"(cnt) : "memory");
}
// release.cluster arrive on peer CTA `rank`'s mbarrier (cumulative over this
// thread's prior stores and, via preceding syncwarp, the warp's stores).
__device__ __forceinline__ void mbar_arrive_release_cluster(uint32_t local_mbar, uint32_t rank) {
    asm volatile("{\n\t.reg .b32 ra;\n\t"
                 "mapa.shared::cluster.u32 ra, %0, %1;\n\t"
                 "mbarrier.arrive.release.cluster.shared::cluster.b64 _, [ra];\n\t}"
                 :: "r"(local_mbar), "r"(rank) : "memory");
}
__device__ __forceinline__ void mbar_wait_parity(uint32_t mbar, uint32_t parity) {
    asm volatile("{\n\t.reg .pred P1;\n\t"
                 "WAIT_LOOP_%=:\n\t"
                 "mbarrier.try_wait.parity.acquire.cluster.shared::cta.b64 P1, [%0], %1, 0x989680;\n\t"
                 "@P1 bra.uni WAIT_DONE_%=;\n\t"
                 "bra.uni WAIT_LOOP_%=;\n\t"
                 "WAIT_DONE_%=:\n\t}" :: "r"(mbar), "r"(parity) : "memory");
}
__device__ __forceinline__ float tanhap(float x) {
    float y; asm("tanh.approx.f32 %0, %1;" : "=f"(y) : "f"(x)); return y;
}
__device__ __forceinline__ float sigap(float x) {
    return fmaf(0.5f, tanhap(0.5f * x), 0.5f);
}
__device__ __forceinline__ void split_bf16(float v, __nv_bfloat16& hi, __nv_bfloat16& lo) {
    hi = __float2bfloat16_rn(v);
    lo = __float2bfloat16_rn(v - __bfloat162float(hi));
}

// ================= wsplit: Wx -> split/transposed packed global =================
__global__ void __launch_bounds__(256)
wsplit_kernel(const float* __restrict__ Wf_x, const float* __restrict__ Wip_x,
              const float* __restrict__ Wit_x, const float* __restrict__ Wo_x)
{
    const int g = blockIdx.x >> 5;
    const int chunk = blockIdx.x & 31;
    const float* W = (g == 0) ? Wf_x : (g == 1) ? Wip_x : (g == 2) ? Wit_x : Wo_x;
    const int i = chunk * 1024 + threadIdx.x * 4;
    #pragma unroll
    for (int q = 0; q < 4; q++) {
        const int n = (i + q) >> 7, k = (i + q) & 127;
        float v = W[(size_t)k * H_SZ + n];
        __nv_bfloat16 hi, lo;
        split_bf16(v, hi, lo);
        g_wxt[g][i + q] = (uint32_t)__bfloat16_as_ushort(hi) |
                          ((uint32_t)__bfloat16_as_ushort(lo) << 16);
    }
}

// ================= precompute: xp = x @ Wx ; block = (t, batch-half) x gate, N=256 =================
__global__ void __launch_bounds__(256, 1)
xproj_kernel(const float* __restrict__ x)
{
    extern __shared__ char smem[];
    __nv_bfloat16* Ax = (__nv_bfloat16*)smem;                  // [128][264] hi|lo
    __nv_bfloat16* Bw = (__nv_bfloat16*)(smem + PC_A_BYTES);   // [256][264] hi|lo

    const int tid = threadIdx.x;
    const int w   = tid >> 5;
    const int l   = tid & 31;
    const int t   = blockIdx.x >> 1;
    const int bh  = (blockIdx.x & 1) * 128;
    const int g   = blockIdx.y;

    {
        const int r    = tid >> 1;
        const int half = (tid & 1) * 64;
        const float* xr = x + ((size_t)(bh + r) * T_SZ + t) * I_SZ + half;
        #pragma unroll 4
        for (int q = 0; q < 64; q++) {
            __nv_bfloat16 hi, lo;
            split_bf16(xr[q], hi, lo);
            Ax[r * SA3 + half + q]       = hi;
            Ax[r * SA3 + 128 + half + q] = lo;
        }
    }
    {
        const uint32_t* src = g_wxt[g] + (size_t)tid * 128;
        #pragma unroll 4
        for (int q = 0; q < 128; q += 2) {
            uint32_t u0 = __ldcg(src + q), u1 = __ldcg(src + q + 1);
            *(uint32_t*)&Bw[tid * SA3 + q]       = (u0 & 0xffffu) | (u1 << 16);
            *(uint32_t*)&Bw[tid * SA3 + 128 + q] = (u0 >> 16) | (u1 & 0xffff0000u);
        }
    }
    __syncthreads();

    const uint32_t a_lane = smem_u32(Ax) +
        (uint32_t)(((16 * w + (l & 7) + 8 * ((l >> 3) & 1)) * SA3 + 8 * (l >> 4)) * 2);
    const uint32_t b_lane = smem_u32(Bw) +
        (uint32_t)((((l & 7) + 8 * (l >> 4)) * SA3 + 8 * ((l >> 3) & 1)) * 2);

    float acc[32][4];
    #pragma unroll
    for (int i = 0; i < 32; i++)
        #pragma unroll
        for (int j = 0; j < 4; j++) acc[i][j] = 0.0f;

    #pragma unroll 1
    for (int kc = 0; kc < 8; kc++) {
        uint32_t ah[4], al[4];
        ldsm4(ah, a_lane + kc * 32);
        ldsm4(al, a_lane + 256 + kc * 32);
        #pragma unroll
        for (int nt = 0; nt < 16; nt++) {
            uint32_t bh4[4], bl4[4];
            uint32_t ba = b_lane + (uint32_t)(nt * 16 * SA3 * 2) + kc * 32;
            ldsm4(bh4, ba);
            ldsm4(bl4, ba + 256);
            mma16816(acc[2 * nt],     ah, bh4 + 0);
            mma16816(acc[2 * nt + 1], ah, bh4 + 2);
            mma16816(acc[2 * nt],     al, bh4 + 0);
            mma16816(acc[2 * nt + 1], al, bh4 + 2);
            mma16816(acc[2 * nt],     ah, bl4 + 0);
            mma16816(acc[2 * nt + 1], ah, bl4 + 2);
        }
    }

    {
        const size_t row0 = (size_t)t * B_SZ + bh + 16 * w + (l >> 2);
        const int    cb   = g * 256 + (l & 3) * 2;
        #pragma unroll
        for (int nt = 0; nt < 16; nt++) {
            *(float2*)&g_xproj[row0 * 1024 + cb + nt * 16]           = make_float2(acc[2*nt][0], acc[2*nt][1]);
            *(float2*)&g_xproj[(row0 + 8) * 1024 + cb + nt * 16]     = make_float2(acc[2*nt][2], acc[2*nt][3]);
            *(float2*)&g_xproj[row0 * 1024 + cb + nt * 16 + 8]       = make_float2(acc[2*nt+1][0], acc[2*nt+1][1]);
            *(float2*)&g_xproj[(row0 + 8) * 1024 + cb + nt * 16 + 8] = make_float2(acc[2*nt+1][2], acc[2*nt+1][3]);
        }
    }
}

// ================= recurrent kernel: barrier-free step loop, direct-L2 B frags =================
__global__ void __launch_bounds__(THREADS2, 1) __cluster_dims__(CLC, 1, 1)
lstm_rec_kernel(const float* __restrict__ Wf_h,  const float* __restrict__ bf,
                const float* __restrict__ Wip_h, const float* __restrict__ bip,
                const float* __restrict__ Wit_h, const float* __restrict__ bit_,
                const float* __restrict__ Wo_h,  const float* __restrict__ bo,
                float* __restrict__ out)
{
    extern __shared__ char smem[];
    __nv_bfloat16* As = (__nv_bfloat16*)smem;
    const uint32_t sb = smem_u32(smem);

    const int tid  = threadIdx.x;
    const int w    = tid >> 5;
    const int l    = tid & 31;
    const int wg   = w >> 3;                 // group 0/1
    const int wl   = w & 7;                  // M-tile within group
    const int cc   = blockIdx.x & (CLC - 1);
    const int grp  = blockIdx.x >> 3;
    const int b0   = grp * 16;
    const int gb   = b0 + wg * NBG;          // group batch base

    // mbarriers: one per group, count = 8 CTAs x 8 warps = 64 arrivals/phase
    if (tid == 0) { mbar_init(sb + MBAR_OFF, 64); mbar_init(sb + MBAR_OFF + 8, 64); }

    // ---- stage A (short-part weights, K=256) hi|lo into SMEM ----
    {
        const int r  = tid >> 2;             // row = 4*h_local + gate
        const int kq = (tid & 3) * 64;
        const int g  = r & 3;
        const int hs = 32 * cc + (r >> 2);
        const float* Wh = (g == 0) ? Wf_h : (g == 1) ? Wip_h : (g == 2) ? Wit_h : Wo_h;
        #pragma unroll 4
        for (int k = kq; k < kq + 64; k++) {
            __nv_bfloat16 hi, lo;
            split_bf16(Wh[(size_t)k * H_SZ + hs], hi, lo);
            As[r * SA2 + k]       = hi;
            As[r * SA2 + 256 + k] = lo;
        }
    }
    // ---- zero step-0 short buffer (own slice) ----
    {
        const int gz = tid >> 8, rz = (tid >> 5) & 7, hz = tid & 31;
        __stcg(&g_short_pack[0][(size_t)(b0 + gz * NBG + rz) * H_SZ + 32 * cc + hz], 0u);
    }
    __syncthreads();

    // ---- A-hi frags to registers (once); A-lo stays in SMEM ----
    const uint32_t a_lane = sb +
        (uint32_t)(((16 * wl + (l & 7) + 8 * ((l >> 3) & 1)) * SA2 + 8 * (l >> 4)) * 2);
    uint32_t ahf[16][4];
    #pragma unroll
    for (int kc = 0; kc < 16; kc++) ldsm4(ahf[kc], a_lane + kc * 32);

    const uint32_t mbar = sb + MBAR_OFF + wg * 8;

    // ---- B fragment base in the exchange buffer: n = l>>2, k cols 2(l&3) ----
    const uint32_t boff = (uint32_t)(gb + (l >> 2)) * H_SZ + 2 * (l & 3);

    // ---- in-register epilogue mapping: lane owns cell (h_loc, bq) ----
    const int h_loc = l >> 3;                // 0..3 within warp
    const int bq    = l & 7;                 // batch within group
    const int hg    = 32 * cc + 4 * wl + h_loc;
    const float biasv[4] = {bf[hg], bip[hg], bit_[hg], bo[hg]};
    float longv = 0.0f;

    __threadfence();
    __syncthreads();
    cluster_sync();

    #pragma unroll 1
    for (int t = 0; t < T_SZ; t++) {
        const int cur = t & 1;
        const int nxt = cur ^ 1;

        // prefetch x-projection for this lane's cell (issued before the wait)
        float xpv[4];
        {
            const float* xr = g_xproj + ((size_t)t * B_SZ + gb + bq) * 1024 + hg;
            #pragma unroll
            for (int g = 0; g < 4; g++) xpv[g] = __ldcg(xr + g * 256);
        }

        // wait for all 64 producer warps' step-t short state
        if (t > 0) mbar_wait_parity(mbar, (t - 1) & 1);

        // ===== GEMM: B fragments loaded DIRECTLY from L2 exchange buffer =====
        const uint32_t* bsrc = g_short_pack[cur] + boff;
        float acc0[4] = {0.f, 0.f, 0.f, 0.f};   // Ahi*Bhi
        float acc1[4] = {0.f, 0.f, 0.f, 0.f};   // Alo*Bhi
        float acc2[4] = {0.f, 0.f, 0.f, 0.f};   // Ahi*Blo
        #pragma unroll 4
        for (int kc = 0; kc < 16; kc++) {
            uint2 va = __ldcg((const uint2*)(bsrc + 16 * kc));      // k pair 2(l&3)
            uint2 vb = __ldcg((const uint2*)(bsrc + 16 * kc + 8));  // k pair +8
            uint32_t bh2[2], bl2[2], alo[4];
            bh2[0] = __byte_perm(va.x, va.y, 0x5410);
            bh2[1] = __byte_perm(vb.x, vb.y, 0x5410);
            bl2[0] = __byte_perm(va.x, va.y, 0x7632);
            bl2[1] = __byte_perm(vb.x, vb.y, 0x7632);
            ldsm4(alo, a_lane + 512 + (uint32_t)kc * 32);
            mma16816(acc0, ahf[kc], bh2);
            mma16816(acc1, alo,     bh2);
            mma16816(acc2, ahf[kc], bl2);
        }
        const float s0 = acc0[0] + acc1[0] + acc2[0];
        const float s1 = acc0[1] + acc1[1] + acc2[1];
        const float s2 = acc0[2] + acc1[2] + acc2[2];
        const float s3 = acc0[3] + acc1[3] + acc2[3];

        // ===== shfl-gather the 4 gate values for this lane's (h_loc, bq) =====
        float z[4];
        #pragma unroll
        for (int g = 0; g < 4; g++) {
            const int row  = 4 * h_loc + g;
            const int srcl = ((row & 7) << 2) | (bq >> 1);
            float t0 = __shfl_sync(0xffffffffu, s0, srcl);
            float t1 = __shfl_sync(0xffffffffu, s1, srcl);
            float t2 = __shfl_sync(0xffffffffu, s2, srcl);
            float t3 = __shfl_sync(0xffffffffu, s3, srcl);
            float lo = (bq & 1) ? t1 : t0;
            float hi = (bq & 1) ? t3 : t2;
            z[g] = (h_loc < 2) ? lo : hi;
        }

        // ===== in-register epilogue =====
        {
            #pragma unroll
            for (int g = 0; g < 4; g++) z[g] += xpv[g] + biasv[g];
            float f  = sigap(z[0]);
            float ip = sigap(z[1]);
            float pt = tanhap(z[2]);
            longv = f * longv + ip * pt;
            float o  = sigap(z[3]);
            float ns = tanhap(longv) * o;

            __nv_bfloat16 hi, lo;
            split_bf16(ns, hi, lo);
            uint32_t pk = (uint32_t)__bfloat16_as_ushort(hi) |
                          ((uint32_t)__bfloat16_as_ushort(lo) << 16);
            const int bbg = gb + bq;
            __stcg(&g_short_pack[nxt][(size_t)bbg * H_SZ + hg], pk);

            if (t == T_SZ - 1) {
                out[(size_t)bbg * H_SZ + hg]                       = ns;
                out[(size_t)B_SZ * H_SZ + (size_t)bbg * H_SZ + hg] = longv;
            }
        }

        // publish: warp-local sync, then lanes 0-7 arrive (release) at all ranks
        __syncwarp();
        if (l < CLC && t < T_SZ - 1)
            mbar_arrive_release_cluster(mbar, (uint32_t)l);
    }
    cluster_sync();  // keep SMEM alive for in-flight remote arrives
}

// ---------------- launch ----------------
extern "C" void kernel_launch(void* const* d_in, const int* in_sizes, int n_in,
                              void* d_out, int out_size)
{
    (void)in_sizes; (void)n_in; (void)out_size;
    const float* x     = (const float*)d_in[0];
    const float* Wf_h  = (const float*)d_in[1];
    const float* Wf_x  = (const float*)d_in[2];
    const float* bf    = (const float*)d_in[3];
    const float* Wip_h = (const float*)d_in[4];
    const float* Wip_x = (const float*)d_in[5];
    const float* bip   = (const float*)d_in[6];
    const float* Wit_h = (const float*)d_in[7];
    const float* Wit_x = (const float*)d_in[8];
    const float* bit_  = (const float*)d_in[9];
    const float* Wo_h  = (const float*)d_in[10];
    const float* Wo_x  = (const float*)d_in[11];
    const float* bo    = (const float*)d_in[12];
    float* out = (float*)d_out;

    cudaFuncSetAttribute(xproj_kernel,
                         cudaFuncAttributeMaxDynamicSharedMemorySize, SMEM3);
    cudaFuncSetAttribute(lstm_rec_kernel,
                         cudaFuncAttributeMaxDynamicSharedMemorySize, SMEM2);

    wsplit_kernel<<<128, 256>>>(Wf_x, Wip_x, Wit_x, Wo_x);

    dim3 pgrid(2048, 4);
    xproj_kernel<<<pgrid, 256, SMEM3>>>(x);

    lstm_rec_kernel<<<GRID_CTAS, THREADS2, SMEM2>>>(
        Wf_h, bf, Wip_h, bip, Wit_h, bit_, Wo_h, bo, out);
}

// round 13
// speedup vs baseline: 2.5400x; 2.5400x over previous
#include <cuda_runtime.h>
#include <cuda_bf16.h>
#include <cstdint>
#include <cstddef>

// ---------------- problem constants ----------------
#define B_SZ   256
#define T_SZ   1024
#define I_SZ   128
#define H_SZ   256
#define CLC    4                 // CTAs per cluster (hidden split: 64 h each)
#define GRID_CTAS 128            // 32 clusters x 8 batch rows
#define THREADS2 512             // 16 warps, one pipeline
#define NBC    8                 // batch rows per cluster

// ---------------- recurrent kernel SMEM ----------------
#define SA2 264                              // stride els; 528B = 33*16B odd -> conflict-free ldsm
#define A_BYTES2  (256 * SA2 * 2)            // 135168 (256 gate rows x 256 k, single bf16)
#define B_OFF2    A_BYTES2
#define B_BYTES2  (NBC * SA2 * 2)            // 4224
#define MBAR_OFF  (B_OFF2 + B_BYTES2 + 64)   // 139456
#define SMEM2     (MBAR_OFF + 64)

// ---------------- precompute kernel SMEM ----------------
#define SA3 264
#define PC_A_BYTES (128 * SA3 * 2)           // 67584 (x tile, M=128)
#define PC_B_BYTES (256 * SA3 * 2)           // 135168 (W tile, N=256)
#define SMEM3 (PC_A_BYTES + PC_B_BYTES)      // 202752

// x-projection scratch: xp[t*B + b][g*256 + h], fp32, 1 GiB
__device__ float g_xproj[268435456];
// single-bf16 short-state exchange, h-pairs packed in u32: [buf][b][h/2]
__device__ uint32_t g_short_pack[2][B_SZ * (H_SZ / 2)];
// pre-split, transposed x-weights: [gate][h=256][k=128] packed (hi | lo<<16)
__device__ uint32_t g_wxt[4][256 * 128];

// ---------------- helpers ----------------
__device__ __forceinline__ uint32_t smem_u32(const void* p) {
    uint32_t a;
    asm("{ .reg .u64 t; cvta.to.shared.u64 t, %1; cvt.u32.u64 %0, t; }" : "=r"(a) : "l"(p));
    return a;
}
__device__ __forceinline__ void cluster_sync() {
    asm volatile("barrier.cluster.arrive.aligned;" ::: "memory");
    asm volatile("barrier.cluster.wait.aligned;"   ::: "memory");
}
__device__ __forceinline__ void ldsm4(uint32_t* r, uint32_t addr) {
    asm volatile("ldmatrix.sync.aligned.m8n8.x4.shared.b16 {%0,%1,%2,%3}, [%4];"
                 : "=r"(r[0]), "=r"(r[1]), "=r"(r[2]), "=r"(r[3]) : "r"(addr));
}
__device__ __forceinline__ void ldsm2(uint32_t* r, uint32_t addr) {
    asm volatile("ldmatrix.sync.aligned.m8n8.x2.shared.b16 {%0,%1}, [%2];"
                 : "=r"(r[0]), "=r"(r[1]) : "r"(addr));
}
__device__ __forceinline__ void mma16816(float* d, const uint32_t* a, const uint32_t* b) {
    asm volatile("mma.sync.aligned.m16n8k16.row.col.f32.bf16.bf16.f32 "
                 "{%0,%1,%2,%3}, {%4,%5,%6,%7}, {%8,%9}, {%0,%1,%2,%3};"
                 : "+f"(d[0]), "+f"(d[1]), "+f"(d[2]), "+f"(d[3])
                 : "r"(a[0]), "r"(a[1]), "r"(a[2]), "r"(a[3]), "r"(b[0]), "r"(b[1]));
}
__device__ __forceinline__ void mbar_init(uint32_t mbar, uint32_t cnt) {
    asm volatile("mbarrier.init.shared.b64 [%0], %1;" :: "r"(mbar), "r"(cnt) : "memory");
}
// release.cluster arrive on peer `rank`'s mbarrier. Preceded by __syncthreads,
// so the release is cumulative over the whole CTA's prior global stores.
__device__ __forceinline__ void mbar_arrive_release_cluster(uint32_t local_mbar, uint32_t rank) {
    asm volatile("{\n\t.reg .b32 ra;\n\t"
                 "mapa.shared::cluster.u32 ra, %0, %1;\n\t"
                 "mbarrier.arrive.release.cluster.shared::cluster.b64 _, [ra];\n\t}"
                 :: "r"(local_mbar), "r"(rank) : "memory");
}
__device__ __forceinline__ void mbar_wait_parity(uint32_t mbar, uint32_t parity) {
    asm volatile("{\n\t.reg .pred P1;\n\t"
                 "WAIT_LOOP_%=:\n\t"
                 "mbarrier.try_wait.parity.acquire.cluster.shared::cta.b64 P1, [%0], %1, 0x989680;\n\t"
                 "@P1 bra.uni WAIT_DONE_%=;\n\t"
                 "bra.uni WAIT_LOOP_%=;\n\t"
                 "WAIT_DONE_%=:\n\t}" :: "r"(mbar), "r"(parity) : "memory");
}
__device__ __forceinline__ float tanhap(float x) {
    float y; asm("tanh.approx.f32 %0, %1;" : "=f"(y) : "f"(x)); return y;
}
__device__ __forceinline__ float sigap(float x) {
    return fmaf(0.5f, tanhap(0.5f * x), 0.5f);
}
__device__ __forceinline__ void split_bf16(float v, __nv_bfloat16& hi, __nv_bfloat16& lo) {
    hi = __float2bfloat16_rn(v);
    lo = __float2bfloat16_rn(v - __bfloat162float(hi));
}

// ================= wsplit: Wx -> split/transposed packed global =================
__global__ void __launch_bounds__(256)
wsplit_kernel(const float* __restrict__ Wf_x, const float* __restrict__ Wip_x,
              const float* __restrict__ Wit_x, const float* __restrict__ Wo_x)
{
    const int g = blockIdx.x >> 5;
    const int chunk = blockIdx.x & 31;
    const float* W = (g == 0) ? Wf_x : (g == 1) ? Wip_x : (g == 2) ? Wit_x : Wo_x;
    const int i = chunk * 1024 + threadIdx.x * 4;
    #pragma unroll
    for (int q = 0; q < 4; q++) {
        const int n = (i + q) >> 7, k = (i + q) & 127;
        float v = W[(size_t)k * H_SZ + n];
        __nv_bfloat16 hi, lo;
        split_bf16(v, hi, lo);
        g_wxt[g][i + q] = (uint32_t)__bfloat16_as_ushort(hi) |
                          ((uint32_t)__bfloat16_as_ushort(lo) << 16);
    }
}

// ================= precompute: xp = x @ Wx (3-term accurate) =================
__global__ void __launch_bounds__(256, 1)
xproj_kernel(const float* __restrict__ x)
{
    extern __shared__ char smem[];
    __nv_bfloat16* Ax = (__nv_bfloat16*)smem;                  // [128][264] hi|lo
    __nv_bfloat16* Bw = (__nv_bfloat16*)(smem + PC_A_BYTES);   // [256][264] hi|lo

    const int tid = threadIdx.x;
    const int w   = tid >> 5;
    const int l   = tid & 31;
    const int t   = blockIdx.x >> 1;
    const int bh  = (blockIdx.x & 1) * 128;
    const int g   = blockIdx.y;

    {
        const int r    = tid >> 1;
        const int half = (tid & 1) * 64;
        const float* xr = x + ((size_t)(bh + r) * T_SZ + t) * I_SZ + half;
        #pragma unroll 4
        for (int q = 0; q < 64; q++) {
            __nv_bfloat16 hi, lo;
            split_bf16(xr[q], hi, lo);
            Ax[r * SA3 + half + q]       = hi;
            Ax[r * SA3 + 128 + half + q] = lo;
        }
    }
    {
        const uint32_t* src = g_wxt[g] + (size_t)tid * 128;
        #pragma unroll 4
        for (int q = 0; q < 128; q += 2) {
            uint32_t u0 = __ldcg(src + q), u1 = __ldcg(src + q + 1);
            *(uint32_t*)&Bw[tid * SA3 + q]       = (u0 & 0xffffu) | (u1 << 16);
            *(uint32_t*)&Bw[tid * SA3 + 128 + q] = (u0 >> 16) | (u1 & 0xffff0000u);
        }
    }
    __syncthreads();

    const uint32_t a_lane = smem_u32(Ax) +
        (uint32_t)(((16 * w + (l & 7) + 8 * ((l >> 3) & 1)) * SA3 + 8 * (l >> 4)) * 2);
    const uint32_t b_lane = smem_u32(Bw) +
        (uint32_t)((((l & 7) + 8 * (l >> 4)) * SA3 + 8 * ((l >> 3) & 1)) * 2);

    float acc[32][4];
    #pragma unroll
    for (int i = 0; i < 32; i++)
        #pragma unroll
        for (int j = 0; j < 4; j++) acc[i][j] = 0.0f;

    #pragma unroll 1
    for (int kc = 0; kc < 8; kc++) {
        uint32_t ah[4], al[4];
        ldsm4(ah, a_lane + kc * 32);
        ldsm4(al, a_lane + 256 + kc * 32);
        #pragma unroll
        for (int nt = 0; nt < 16; nt++) {
            uint32_t bh4[4], bl4[4];
            uint32_t ba = b_lane + (uint32_t)(nt * 16 * SA3 * 2) + kc * 32;
            ldsm4(bh4, ba);
            ldsm4(bl4, ba + 256);
            mma16816(acc[2 * nt],     ah, bh4 + 0);
            mma16816(acc[2 * nt + 1], ah, bh4 + 2);
            mma16816(acc[2 * nt],     al, bh4 + 0);
            mma16816(acc[2 * nt + 1], al, bh4 + 2);
            mma16816(acc[2 * nt],     ah, bl4 + 0);
            mma16816(acc[2 * nt + 1], ah, bl4 + 2);
        }
    }

    {
        const size_t row0 = (size_t)t * B_SZ + bh + 16 * w + (l >> 2);
        const int    cb   = g * 256 + (l & 3) * 2;
        #pragma unroll
        for (int nt = 0; nt < 16; nt++) {
            *(float2*)&g_xproj[row0 * 1024 + cb + nt * 16]           = make_float2(acc[2*nt][0], acc[2*nt][1]);
            *(float2*)&g_xproj[(row0 + 8) * 1024 + cb + nt * 16]     = make_float2(acc[2*nt][2], acc[2*nt][3]);
            *(float2*)&g_xproj[row0 * 1024 + cb + nt * 16 + 8]       = make_float2(acc[2*nt+1][0], acc[2*nt+1][1]);
            *(float2*)&g_xproj[(row0 + 8) * 1024 + cb + nt * 16 + 8] = make_float2(acc[2*nt+1][2], acc[2*nt+1][3]);
        }
    }
}

// ================= recurrent kernel: cluster=4, single-term bf16, 16 warps =================
__global__ void __launch_bounds__(THREADS2, 1) __cluster_dims__(CLC, 1, 1)
lstm_rec_kernel(const float* __restrict__ Wf_h,  const float* __restrict__ bf,
                const float* __restrict__ Wip_h, const float* __restrict__ bip,
                const float* __restrict__ Wit_h, const float* __restrict__ bit_,
                const float* __restrict__ Wo_h,  const float* __restrict__ bo,
                float* __restrict__ out)
{
    extern __shared__ char smem[];
    __nv_bfloat16* As = (__nv_bfloat16*)smem;
    __nv_bfloat16* Bs = (__nv_bfloat16*)(smem + B_OFF2);
    const uint32_t sb = smem_u32(smem);

    const int tid = threadIdx.x;
    const int w   = tid >> 5;                // M-tile: rows 16w..16w+15
    const int l   = tid & 31;
    const int cc  = blockIdx.x & (CLC - 1);  // hidden-slice owner (64 h)
    const int grp = blockIdx.x >> 2;         // 32 clusters
    const int b0  = grp * NBC;

    if (tid == 0) mbar_init(sb + MBAR_OFF, CLC);

    // ---- stage A (short-part weights, K=256, SINGLE bf16) ----
    // row r = 4*h_local + gate, h_local in [0,64)
    {
        const int r  = tid >> 1;             // 0..255
        const int kh = (tid & 1) * 128;
        const int g  = r & 3;
        const int hs = 64 * cc + (r >> 2);
        const float* Wh = (g == 0) ? Wf_h : (g == 1) ? Wip_h : (g == 2) ? Wit_h : Wo_h;
        #pragma unroll 4
        for (int k = kh; k < kh + 128; k++)
            As[r * SA2 + k] = __float2bfloat16_rn(Wh[(size_t)k * H_SZ + hs]);
    }
    // ---- zero step-0 short buffer (own slice: 8 b x 32 u32 h-pairs) ----
    {
        const int rz = tid >> 6, pz = tid & 63;   // 8 rows x 64 -> but only 32 pairs per slice
        if (pz < 32)
            __stcg(&g_short_pack[0][(size_t)(b0 + rz) * 128 + 32 * cc + pz], 0u);
    }
    __syncthreads();

    const uint32_t a_lane = sb +
        (uint32_t)(((16 * w + (l & 7) + 8 * ((l >> 3) & 1)) * SA2 + 8 * (l >> 4)) * 2);
    const uint32_t b_lane = sb + B_OFF2 +
        (uint32_t)(((l & 7) * SA2 + ((l >> 3) & 1) * 8) * 2);
    const uint32_t mbar = sb + MBAR_OFF;

    // ---- epilogue mapping: 1 cell per lane: h_loc = l>>3, bq = l&7 ----
    const int h_loc = l >> 3;
    const int bq    = l & 7;
    const int hg    = 64 * cc + 4 * w + h_loc;
    const float biasv[4] = {bf[hg], bip[hg], bit_[hg], bo[hg]};
    float longv = 0.0f;

    __threadfence();
    __syncthreads();
    cluster_sync();

    #pragma unroll 1
    for (int t = 0; t < T_SZ; t++) {
        const int cur = t & 1;
        const int nxt = cur ^ 1;

        // prefetch x-projection (issued before the wait)
        float xpv[4];
        {
            const float* xr = g_xproj + ((size_t)t * B_SZ + b0 + bq) * 1024 + hg;
            #pragma unroll
            for (int g = 0; g < 4; g++) xpv[g] = __ldcg(xr + g * 256);
        }

        // wait for all 4 CTAs' step-t short state
        if (t > 0) mbar_wait_parity(mbar, (t - 1) & 1);

        // ===== stage B tile [8 b][256 h] single bf16 from L2 =====
        {
            const int row = tid >> 6;                  // 0..7
            const int po  = (tid & 63) * 2;            // u32 pair offset
            uint2 v = __ldcg((const uint2*)(g_short_pack[cur] + (size_t)(b0 + row) * 128 + po));
            *(uint2*)&Bs[row * SA2 + po * 2] = v;      // 4 bf16
        }
        __syncthreads();

        // ===== GEMM: M=16 (this warp), N=8, K=256, single term, 2 chains =====
        float acc_e[4] = {0.f, 0.f, 0.f, 0.f};
        float acc_o[4] = {0.f, 0.f, 0.f, 0.f};
        #pragma unroll
        for (int kc = 0; kc < 16; kc += 2) {
            uint32_t af0[4], af1[4], b0r[2], b1r[2];
            ldsm4(af0, a_lane + (uint32_t)kc * 32);
            ldsm2(b0r, b_lane + (uint32_t)kc * 32);
            ldsm4(af1, a_lane + (uint32_t)(kc + 1) * 32);
            ldsm2(b1r, b_lane + (uint32_t)(kc + 1) * 32);
            mma16816(acc_e, af0, b0r);
            mma16816(acc_o, af1, b1r);
        }
        const float s0 = acc_e[0] + acc_o[0];
        const float s1 = acc_e[1] + acc_o[1];
        const float s2 = acc_e[2] + acc_o[2];
        const float s3 = acc_e[3] + acc_o[3];

        // ===== shfl-gather the 4 gate values for this lane's (h_loc, bq) =====
        float z[4];
        #pragma unroll
        for (int g = 0; g < 4; g++) {
            const int row  = 4 * h_loc + g;
            const int srcl = ((row & 7) << 2) | (bq >> 1);
            float t0 = __shfl_sync(0xffffffffu, s0, srcl);
            float t1 = __shfl_sync(0xffffffffu, s1, srcl);
            float t2 = __shfl_sync(0xffffffffu, s2, srcl);
            float t3 = __shfl_sync(0xffffffffu, s3, srcl);
            float lo = (bq & 1) ? t1 : t0;
            float hi = (bq & 1) ? t3 : t2;
            z[g] = (h_loc < 2) ? lo : hi;
        }

        // ===== in-register epilogue =====
        {
            #pragma unroll
            for (int g = 0; g < 4; g++) z[g] += xpv[g] + biasv[g];
            float f  = sigap(z[0]);
            float ip = sigap(z[1]);
            float pt = tanhap(z[2]);
            longv = f * longv + ip * pt;
            float o  = sigap(z[3]);
            float ns = tanhap(longv) * o;

            // pack h-pairs: lanes l and l^8 hold h and h^1 (h_loc differs by 1)
            uint32_t mybits = (uint32_t)__bfloat16_as_ushort(__float2bfloat16_rn(ns));
            uint32_t other  = __shfl_xor_sync(0xffffffffu, mybits, 8);
            if ((h_loc & 1) == 0) {
                uint32_t pk = mybits | (other << 16);
                __stcg(&g_short_pack[nxt][(size_t)(b0 + bq) * 128 + (hg >> 1)], pk);
            }

            if (t == T_SZ - 1) {
                const int bbg = b0 + bq;
                out[(size_t)bbg * H_SZ + hg]                       = ns;
                out[(size_t)B_SZ * H_SZ + (size_t)bbg * H_SZ + hg] = longv;
            }
        }
        __syncthreads();

        // publish: 4 parallel release arrives (one per rank), tids 0-3
        if (tid < CLC && t < T_SZ - 1)
            mbar_arrive_release_cluster(mbar, (uint32_t)tid);
    }
    cluster_sync();  // keep SMEM alive for in-flight remote arrives
}

// ---------------- launch ----------------
extern "C" void kernel_launch(void* const* d_in, const int* in_sizes, int n_in,
                              void* d_out, int out_size)
{
    (void)in_sizes; (void)n_in; (void)out_size;
    const float* x     = (const float*)d_in[0];
    const float* Wf_h  = (const float*)d_in[1];
    const float* Wf_x  = (const float*)d_in[2];
    const float* bf    = (const float*)d_in[3];
    const float* Wip_h = (const float*)d_in[4];
    const float* Wip_x = (const float*)d_in[5];
    const float* bip   = (const float*)d_in[6];
    const float* Wit_h = (const float*)d_in[7];
    const float* Wit_x = (const float*)d_in[8];
    const float* bit_  = (const float*)d_in[9];
    const float* Wo_h  = (const float*)d_in[10];
    const float* Wo_x  = (const float*)d_in[11];
    const float* bo    = (const float*)d_in[12];
    float* out = (float*)d_out;

    cudaFuncSetAttribute(xproj_kernel,
                         cudaFuncAttributeMaxDynamicSharedMemorySize, SMEM3);
    cudaFuncSetAttribute(lstm_rec_kernel,
                         cudaFuncAttributeMaxDynamicSharedMemorySize, SMEM2);

    wsplit_kernel<<<128, 256>>>(Wf_x, Wip_x, Wit_x, Wo_x);

    dim3 pgrid(2048, 4);
    xproj_kernel<<<pgrid, 256, SMEM3>>>(x);

    lstm_rec_kernel<<<GRID_CTAS, THREADS2, SMEM2>>>(
        Wf_h, bf, Wip_h, bip, Wit_h, bit_, Wo_h, bo, out);
}